// round 12
// baseline (speedup 1.0000x reference)
#include <cuda_runtime.h>
#include <math.h>
#include <cstdint>

#define NC    21
#define HW    (512 * 512)          // 2^18
#define NB    8
#define NPIX  (NB * HW)            // 2,097,152
#define TPB   256
#define TILE  512                  // pixels per CTA tile
#define NBLK  (NPIX / TILE)        // 4096
#define DEPTH 8                    // smem pipeline stages (covers all slots)
#define CHUNK (TILE * 4)           // 2048 bytes per channel per tensor

// dynamic smem layout (bytes)
#define OFF_P    0
#define OFF_T    (DEPTH * CHUNK)           // 16384
#define OFF_MBAR (2 * DEPTH * CHUNK)       // 32768 (8B aligned)
#define SMEM_DYN (OFF_MBAR + DEPTH * 8)    // 32832

// Allocation-free scratch; zero at module load, reset by the last block.
__device__ float        g_cls_sum[NC];
__device__ int          g_cls_cnt[NC];
__device__ unsigned int g_done;

__device__ __forceinline__ uint32_t smem_u32(const void* p) {
    uint32_t a;
    asm("{ .reg .u64 t; cvta.to.shared.u64 t, %1; cvt.u32.u64 %0, t; }"
        : "=r"(a) : "l"(p));
    return a;
}

__device__ __forceinline__ void mbar_init(uint32_t mbar, uint32_t cnt) {
    asm volatile("mbarrier.init.shared.b64 [%0], %1;" :: "r"(mbar), "r"(cnt) : "memory");
}
__device__ __forceinline__ void mbar_expect_tx(uint32_t mbar, uint32_t bytes) {
    asm volatile("mbarrier.arrive.expect_tx.shared.b64 _, [%0], %1;"
                 :: "r"(mbar), "r"(bytes) : "memory");
}
__device__ __forceinline__ void mbar_wait(uint32_t mbar, uint32_t parity) {
    asm volatile(
        "{\n\t"
        ".reg .pred P1;\n\t"
        "WAIT_LOOP_%=:\n\t"
        "mbarrier.try_wait.parity.acquire.cta.shared::cta.b64 P1, [%0], %1, 0x989680;\n\t"
        "@P1 bra.uni WAIT_DONE_%=;\n\t"
        "bra.uni WAIT_LOOP_%=;\n\t"
        "WAIT_DONE_%=:\n\t"
        "}"
        :: "r"(mbar), "r"(parity) : "memory");
}
__device__ __forceinline__ void bulk_cp(uint32_t dst, const void* src,
                                        uint32_t bytes, uint32_t mbar) {
    asm volatile(
        "cp.async.bulk.shared::cta.global.mbarrier::complete_tx::bytes [%0], [%1], %2, [%3];"
        :: "r"(dst), "l"(src), "r"(bytes), "r"(mbar) : "memory");
}

__global__ __launch_bounds__(TPB, 6)
void cbfocal_fused_kernel(const float* __restrict__ pred,
                          const float* __restrict__ target,
                          float* __restrict__ out) {
    extern __shared__ char dsm[];
    float* bufP = (float*)(dsm + OFF_P);
    float* bufT = (float*)(dsm + OFF_T);
    const uint32_t sbase = smem_u32(dsm);
    const uint32_t mbar0 = sbase + OFF_MBAR;

    __shared__ float s_sum[NC];
    __shared__ int   s_cnt[NC];
    __shared__ bool  s_last;

    int t = threadIdx.x;
    if (t < NC) { s_sum[t] = 0.0f; s_cnt[t] = 0; }
    if (t == 0) {
        #pragma unroll
        for (int i = 0; i < DEPTH; i++) mbar_init(mbar0 + 8 * i, 1);
        asm volatile("fence.proxy.async.shared::cta;" ::: "memory");
    }
    __syncthreads();

    // This CTA's tile: TILE consecutive pixels, all in one batch (HW % TILE == 0).
    long base = (long)blockIdx.x * TILE;
    int  b    = (int)(base >> 18);
    int  hw   = (int)(base & (HW - 1));
    const float* psrc = pred   + (((long)b * NC) << 18) + hw;
    const float* tsrc = target + (((long)b * NC) << 18) + hw;

    // Prologue: t0 fills all DEPTH stages with channels 0..7.
    if (t == 0) {
        #pragma unroll
        for (int c = 0; c < DEPTH; c++) {
            uint32_t mb = mbar0 + 8 * c;
            mbar_expect_tx(mb, 2 * CHUNK);
            bulk_cp(sbase + OFF_P + c * CHUNK, psrc + ((long)c << 18), CHUNK, mb);
            bulk_cp(sbase + OFF_T + c * CHUNK, tsrc + ((long)c << 18), CHUNK, mb);
        }
    }

    // Online sum-of-exp over 2 pixels/thread (t and t+256 within the tile).
    float s0 = 0.f, s1 = 0.f, vc0 = 0.f, vc1 = 0.f;
    int   cls0 = 0, cls1 = 0;

    #pragma unroll
    for (int c = 0; c < NC; c++) {
        int slot = c % DEPTH;
        mbar_wait(mbar0 + 8 * slot, (c / DEPTH) & 1);

        float pv0 = bufP[slot * TILE + t];
        float pv1 = bufP[slot * TILE + TPB + t];
        float tv0 = bufT[slot * TILE + t];
        float tv1 = bufT[slot * TILE + TPB + t];

        s0 += __expf(pv0);
        s1 += __expf(pv1);
        if (tv0 > 0.5f) { cls0 = c; vc0 = pv0; }
        if (tv1 > 0.5f) { cls1 = c; vc1 = pv1; }

        __syncthreads();   // all threads done with this slot
        int cn = c + DEPTH;
        if (t == 0 && cn < NC) {
            uint32_t mb = mbar0 + 8 * slot;
            mbar_expect_tx(mb, 2 * CHUNK);
            bulk_cp(sbase + OFF_P + slot * CHUNK, psrc + ((long)cn << 18), CHUNK, mb);
            bulk_cp(sbase + OFF_T + slot * CHUNK, tsrc + ((long)cn << 18), CHUNK, mb);
        }
    }

    {
        float lp, p, om;
        lp = vc0 - __logf(s0); p = __expf(lp); om = 1.f - p;
        atomicAdd(&s_sum[cls0], om * om * lp); atomicAdd(&s_cnt[cls0], 1);
        lp = vc1 - __logf(s1); p = __expf(lp); om = 1.f - p;
        atomicAdd(&s_sum[cls1], om * om * lp); atomicAdd(&s_cnt[cls1], 1);
    }
    __syncthreads();

    if (t < NC) {
        atomicAdd(&g_cls_sum[t], s_sum[t]);
        atomicAdd(&g_cls_cnt[t], s_cnt[t]);
    }

    // Last-block epilogue: weighted reduction + reset.
    __threadfence();
    if (t == 0) {
        unsigned int prev = atomicAdd(&g_done, 1u);
        s_last = (prev == (unsigned int)(gridDim.x - 1));
    }
    __syncthreads();

    if (s_last && t < 32) {
        const double n    = (double)NPIX;
        const double beta = (n - 1.0) / n;

        double val = 0.0;
        if (t < NC) {
            double w = (1.0 - beta) / (1.0 - pow(beta, (double)g_cls_cnt[t]) + 1e-6);
            val = w * (double)g_cls_sum[t];
        }
        #pragma unroll
        for (int o = 16; o > 0; o >>= 1) {
            val += __shfl_down_sync(0xffffffffu, val, o);
        }
        if (t < NC) { g_cls_sum[t] = 0.0f; g_cls_cnt[t] = 0; }
        if (t == 0) {
            g_done = 0u;
            out[0] = (float)(-val / n);
        }
    }
}

extern "C" void kernel_launch(void* const* d_in, const int* in_sizes, int n_in,
                              void* d_out, int out_size) {
    const float* pred   = (const float*)d_in[0];
    const float* target = (const float*)d_in[1];
    cudaFuncSetAttribute(cbfocal_fused_kernel,
                         cudaFuncAttributeMaxDynamicSharedMemorySize, SMEM_DYN);
    cbfocal_fused_kernel<<<NBLK, TPB, SMEM_DYN>>>(pred, target, (float*)d_out);
}